// round 11
// baseline (speedup 1.0000x reference)
#include <cuda_runtime.h>
#include <cstdint>

// preds/target = [B=8, C=21, H=512, W=512] fp32, contiguous.
// R11: decouple DRAM issue from consumption. Thread 0 streams 8KB+8KB units
// into smem via cp.async.bulk (mbarrier complete_tx); 256 threads count from
// smem. Double-buffered stages; work-stealing cursor; per-class smem acc;
// once-per-block global commit; fused last-block finalize + self-reset.

#define NCLS 21
#define UNIT_FLOATS 2048
#define UNIT_BYTES  8192                       // per tensor
#define SLOT_BYTES  (2 * UNIT_BYTES)           // preds + targ
#define NSTAGE 2
#define UNITS_PER_SLAB 128                     // 262144 / 2048
#define TOTAL_UNITS (168 * UNITS_PER_SLAB)     // 21504
#define THREADS 256
#define BLOCKS_PER_SM 6
#define GRID_BLOCKS (148 * BLOCKS_PER_SM)      // 888
#define INVALID_U 0xFFFFFFFFu

// g_cnt layout: [cls*3 + 0]=pred_sum, +1=target_sum, +2=intersection
__device__ int g_cnt[NCLS * 3];
__device__ unsigned int g_next;                // work-stealing cursor
__device__ unsigned int g_done;                // completion count

__device__ __forceinline__ unsigned smem_u32(const void* p) {
    unsigned a;
    asm("{ .reg .u64 t; cvta.to.shared.u64 t, %1; cvt.u32.u64 %0, t; }"
        : "=r"(a) : "l"(p));
    return a;
}

__device__ __forceinline__ void mbar_init(unsigned m, unsigned cnt) {
    asm volatile("mbarrier.init.shared.b64 [%0], %1;" :: "r"(m), "r"(cnt) : "memory");
}
__device__ __forceinline__ void mbar_arrive_expect_tx(unsigned m, unsigned tx) {
    asm volatile("mbarrier.arrive.expect_tx.release.cta.shared.b64 _, [%0], %1;"
                 :: "r"(m), "r"(tx) : "memory");
}
__device__ __forceinline__ void mbar_arrive(unsigned m) {
    asm volatile("mbarrier.arrive.release.cta.shared.b64 _, [%0];"
                 :: "r"(m) : "memory");
}
__device__ __forceinline__ void mbar_wait(unsigned m, unsigned parity) {
    unsigned done;
    asm volatile(
        "{\n\t.reg .pred p;\n\t"
        "mbarrier.try_wait.parity.acquire.cta.shared::cta.b64 p, [%1], %2;\n\t"
        "selp.b32 %0, 1, 0, p;\n\t}"
        : "=r"(done) : "r"(m), "r"(parity) : "memory");
    if (!done) {
        asm volatile(
            "{\n\t.reg .pred P1;\n\t"
            "W_%=:\n\t"
            "mbarrier.try_wait.parity.acquire.cta.shared::cta.b64 P1, [%0], %1, 0x989680;\n\t"
            "@P1 bra.uni D_%=;\n\t"
            "bra.uni W_%=;\n\t"
            "D_%=:\n\t}"
            :: "r"(m), "r"(parity) : "memory");
    }
}
__device__ __forceinline__ void bulk_copy(unsigned dst, const void* src,
                                          unsigned bytes, unsigned mbar) {
    asm volatile(
        "cp.async.bulk.shared::cta.global.mbarrier::complete_tx::bytes "
        "[%0], [%1], %2, [%3];"
        :: "r"(dst), "l"(src), "r"(bytes), "r"(mbar) : "memory");
}

__global__ __launch_bounds__(THREADS, BLOCKS_PER_SM) void jidx_fused_kernel(
    const float* __restrict__ preds,
    const float* __restrict__ targ,
    float* __restrict__ out)
{
    __shared__ __align__(16) char slots[NSTAGE * SLOT_BYTES];
    __shared__ __align__(8)  unsigned long long mbar_store[NSTAGE];
    __shared__ unsigned s_unit[NSTAGE];
    __shared__ int s_acc[NCLS * 3];
    __shared__ int s_last;

    const int tid = threadIdx.x;
    const unsigned slots_a = smem_u32(slots);
    const unsigned mbar_a  = smem_u32(mbar_store);

    for (int i = tid; i < NCLS * 3; i += THREADS) s_acc[i] = 0;
    if (tid == 0) {
        mbar_init(mbar_a + 0, 1);
        mbar_init(mbar_a + 8, 1);
    }
    __syncthreads();

    // Prologue: fill both stages.
    if (tid == 0) {
        #pragma unroll
        for (int s = 0; s < NSTAGE; ++s) {
            unsigned u = atomicAdd(&g_next, 1u);
            if (u < TOTAL_UNITS) {
                s_unit[s] = u;
                mbar_arrive_expect_tx(mbar_a + 8 * s, SLOT_BYTES);
                bulk_copy(slots_a + s * SLOT_BYTES,
                          preds + (size_t)u * UNIT_FLOATS, UNIT_BYTES,
                          mbar_a + 8 * s);
                bulk_copy(slots_a + s * SLOT_BYTES + UNIT_BYTES,
                          targ + (size_t)u * UNIT_FLOATS, UNIT_BYTES,
                          mbar_a + 8 * s);
            } else {
                s_unit[s] = INVALID_U;
                mbar_arrive(mbar_a + 8 * s);
            }
        }
    }

    for (int k = 0; ; ++k) {
        const int s = k & 1;
        const unsigned ph = (unsigned)(k >> 1) & 1u;
        mbar_wait(mbar_a + 8 * s, ph);

        const unsigned u = s_unit[s];
        if (u == INVALID_U) break;                   // uniform exit

        const int cls = (int)((u >> 7) % NCLS);      // slab = u / 128
        const float4* p4 = (const float4*)(slots + s * SLOT_BYTES);
        const float4* t4 = (const float4*)(slots + s * SLOT_BYTES + UNIT_BYTES);

        // Per thread: 2 float4 per tensor. Per-warp count <= 256 < 1023,
        // so packed = ps | ts<<10 | inter<<20 in one int.
        int packed = 0;
        #pragma unroll
        for (int j = 0; j < 2; ++j) {
            float4 p = p4[tid + j * THREADS];
            float4 t = t4[tid + j * THREADS];
            int p0 = p.x >= 0.5f, p1 = p.y >= 0.5f, p2 = p.z >= 0.5f, p3 = p.w >= 0.5f;
            int t0 = t.x == 1.0f, t1 = t.y == 1.0f, t2 = t.z == 1.0f, t3 = t.w == 1.0f;
            packed += (p0 + p1 + p2 + p3)
                    + ((t0 + t1 + t2 + t3) << 10)
                    + (((p0 & t0) + (p1 & t1) + (p2 & t2) + (p3 & t3)) << 20);
        }
        #pragma unroll
        for (int o = 16; o > 0; o >>= 1)
            packed += __shfl_down_sync(0xffffffffu, packed, o);
        if ((tid & 31) == 0) {
            atomicAdd(&s_acc[cls * 3 + 0],  packed        & 1023);
            atomicAdd(&s_acc[cls * 3 + 1], (packed >> 10) & 1023);
            atomicAdd(&s_acc[cls * 3 + 2], (packed >> 20) & 1023);
        }

        __syncthreads();     // all threads done reading slot s
        if (tid == 0) {      // refill slot s for iteration k+2
            unsigned nu = atomicAdd(&g_next, 1u);
            if (nu < TOTAL_UNITS) {
                s_unit[s] = nu;
                mbar_arrive_expect_tx(mbar_a + 8 * s, SLOT_BYTES);
                bulk_copy(slots_a + s * SLOT_BYTES,
                          preds + (size_t)nu * UNIT_FLOATS, UNIT_BYTES,
                          mbar_a + 8 * s);
                bulk_copy(slots_a + s * SLOT_BYTES + UNIT_BYTES,
                          targ + (size_t)nu * UNIT_FLOATS, UNIT_BYTES,
                          mbar_a + 8 * s);
            } else {
                s_unit[s] = INVALID_U;
                mbar_arrive(mbar_a + 8 * s);
            }
        }
    }

    // Drain block totals to global (once per block, 63 atomics).
    __syncthreads();
    for (int i = tid; i < NCLS * 3; i += THREADS)
        atomicAdd(&g_cnt[i], s_acc[i]);

    // Completion protocol.
    if (tid == 0) {
        __threadfence();
        unsigned t = atomicAdd(&g_done, 1u);
        s_last = (t == (unsigned)(GRID_BLOCKS - 1));
    }
    __syncthreads();

    if (s_last) {
        __threadfence();
        if (tid < NCLS) {
            float ps    = (float)g_cnt[tid * 3 + 0];
            float ts    = (float)g_cnt[tid * 3 + 1];
            float inter = (float)g_cnt[tid * 3 + 2];
            float uni = ps + ts - inter;
            out[tid] = (uni == 0.0f) ? __int_as_float(0x7fc00000)  // NaN
                                     : inter / fmaxf(uni, 1.0f);
            g_cnt[tid * 3 + 0] = 0;
            g_cnt[tid * 3 + 1] = 0;
            g_cnt[tid * 3 + 2] = 0;
        }
        if (tid == 0) { g_next = 0u; g_done = 0u; }
    }
}

extern "C" void kernel_launch(void* const* d_in, const int* in_sizes, int n_in,
                              void* d_out, int out_size) {
    const float* preds = (const float*)d_in[0];
    const float* targ  = (const float*)d_in[1];
    float* out = (float*)d_out;

    jidx_fused_kernel<<<GRID_BLOCKS, THREADS>>>(preds, targ, out);
}